// round 15
// baseline (speedup 1.0000x reference)
#include <cuda_runtime.h>
#include <cuda_bf16.h>
#include <cstdint>

#define BATCH    1024
#define NS       64
#define EM_T     65536u      // floats per timestep (B*NS)
#define SHIFT_C  4.5f

__device__ int g_perm[BATCH];   // rank (desc by length) -> batch index

// ---- rank by length (descending), ties by index: perm is a bijection ----
__global__ void rank_kernel(const int* __restrict__ seq) {
    __shared__ int len[BATCH];
    const int tid = threadIdx.x;             // 128 threads
    for (int j = tid; j < BATCH; j += 128) len[j] = seq[j];
    __syncthreads();
    const int i  = blockIdx.x * 128 + tid;
    const int li = len[i];
    int r = 0;
#pragma unroll 8
    for (int j = 0; j < BATCH; j++) {
        int lj = len[j];
        r += (int)((lj > li) | ((lj == li) & (j < i)));
    }
    g_perm[r] = i;
}

__device__ __forceinline__ unsigned pack_bf2(float lo, float hi) {
    __nv_bfloat162 h = __floats2bfloat162_rn(lo, hi);
    return *reinterpret_cast<unsigned*>(&h);
}
__device__ __forceinline__ float bf16lo_f(unsigned u) {
    __nv_bfloat162 h = *reinterpret_cast<__nv_bfloat162*>(&u);
    return __low2float(h);
}
__device__ __forceinline__ void mma16816(float* d, const unsigned* a,
                                         unsigned b0, unsigned b1) {
    asm("mma.sync.aligned.m16n8k16.row.col.f32.bf16.bf16.f32 "
        "{%0,%1,%2,%3}, {%4,%5,%6,%7}, {%8,%9}, {%0,%1,%2,%3};"
        : "+f"(d[0]), "+f"(d[1]), "+f"(d[2]), "+f"(d[3])
        : "r"(a[0]), "r"(a[1]), "r"(a[2]), "r"(a[3]), "r"(b0), "r"(b1));
}

// Block = one group of 8 length-sorted sequences, 128 threads:
//   w0: fwd consumer (full 64x8 tick via 16 MMA, warp-private, no bar.sync)
//   w1: bwd consumer
//   w2: fwd emission producer (exp(em) into 8-deep smem ring)
//   w3: bwd emission producer
__global__ void __launch_bounds__(128, 1)
crf_forward_kernel(const float* __restrict__ em,
                   const int*   __restrict__ seq,
                   const float* __restrict__ start,
                   const float* __restrict__ stop,
                   const float* __restrict__ trans,
                   float*       __restrict__ out)
{
    __shared__ uint32_t vbuf[2][2][256];          // [dir][parity][kpair*8+n]
    __shared__ float2   ering[2][8][64][4];       // [dir][slot][row][colpair]
    __shared__ float    meetA[64][8], meetB[64][8];
    __shared__ float    sC[2][8];
    __shared__ int      bat[8], Lsh[8];
    __shared__ volatile int ready[2][8];
    __shared__ volatile int consumed[2];

    const int tid  = threadIdx.x;
    const int w    = tid >> 5;
    const int lane = tid & 31;
    const int q    = lane >> 2;   // 0..7
    const int p    = lane & 3;    // 0..3

    if (tid < 8) {
        int b = g_perm[8 * blockIdx.x + tid];
        bat[tid] = b;
        Lsh[tid] = seq[b];
    }
    if (tid == 0) { consumed[0] = 0; consumed[1] = 0; }
    if (tid < 16) ready[tid >> 3][tid & 7] = 0;
    __syncthreads();

    const int dir = w & 1;        // 0 fwd, 1 bwd
    int Tmax = 0;
#pragma unroll
    for (int j = 0; j < 8; j++) {
        int Lj = Lsh[j];
        int s  = dir ? (Lj - 1 - (Lj >> 1)) : (Lj >> 1);
        Tmax = max(Tmax, s);
    }

    if (w < 2) {
        // ============================ CONSUMER ============================
        const int c0 = 2 * p, c1 = c0 + 1;
        const int b0 = bat[c0], b1 = bat[c1];
        const int L0 = Lsh[c0], L1 = Lsh[c1];
        const int S0 = dir ? (L0 - 1 - (L0 >> 1)) : (L0 >> 1);
        const int S1 = dir ? (L1 - 1 - (L1 >> 1)) : (L1 >> 1);

        // A fragments: 4 M-tiles x 4 k-tiles (fwd: rows of E; bwd: rows of E^T)
        unsigned afr[4][4][4];
#pragma unroll
        for (int m = 0; m < 4; m++) {
            int R0 = 16 * m + q, R1 = R0 + 8;
#pragma unroll
            for (int kt = 0; kt < 4; kt++) {
                int kc = 16 * kt + 2 * p;
                if (dir == 0) {
                    afr[m][kt][0] = pack_bf2(__expf(__ldg(trans + R0 * NS + kc) - SHIFT_C),
                                             __expf(__ldg(trans + R0 * NS + kc + 1) - SHIFT_C));
                    afr[m][kt][1] = pack_bf2(__expf(__ldg(trans + R1 * NS + kc) - SHIFT_C),
                                             __expf(__ldg(trans + R1 * NS + kc + 1) - SHIFT_C));
                    afr[m][kt][2] = pack_bf2(__expf(__ldg(trans + R0 * NS + kc + 8) - SHIFT_C),
                                             __expf(__ldg(trans + R0 * NS + kc + 9) - SHIFT_C));
                    afr[m][kt][3] = pack_bf2(__expf(__ldg(trans + R1 * NS + kc + 8) - SHIFT_C),
                                             __expf(__ldg(trans + R1 * NS + kc + 9) - SHIFT_C));
                } else {
                    afr[m][kt][0] = pack_bf2(__expf(__ldg(trans + kc * NS + R0) - SHIFT_C),
                                             __expf(__ldg(trans + (kc + 1) * NS + R0) - SHIFT_C));
                    afr[m][kt][1] = pack_bf2(__expf(__ldg(trans + kc * NS + R1) - SHIFT_C),
                                             __expf(__ldg(trans + (kc + 1) * NS + R1) - SHIFT_C));
                    afr[m][kt][2] = pack_bf2(__expf(__ldg(trans + (kc + 8) * NS + R0) - SHIFT_C),
                                             __expf(__ldg(trans + (kc + 9) * NS + R0) - SHIFT_C));
                    afr[m][kt][3] = pack_bf2(__expf(__ldg(trans + (kc + 8) * NS + R1) - SHIFT_C),
                                             __expf(__ldg(trans + (kc + 9) * NS + R1) - SHIFT_C));
                }
            }
        }

        // master state + init store
        float V[4][4];
        float Ca = 0.0f, Cc = 0.0f;
        float sv[4][4];
#pragma unroll
        for (int m = 0; m < 4; m++) {
            int R0 = 16 * m + q, R1 = R0 + 8;
            if (dir == 0) {
                float s0v = __ldg(start + R0), s1v = __ldg(start + R1);
                V[m][0] = __expf(s0v + __ldg(em + (unsigned)b0 * NS + R0));
                V[m][1] = __expf(s0v + __ldg(em + (unsigned)b1 * NS + R0));
                V[m][2] = __expf(s1v + __ldg(em + (unsigned)b0 * NS + R1));
                V[m][3] = __expf(s1v + __ldg(em + (unsigned)b1 * NS + R1));
                sv[m][0] = (1 <= S0) ? V[m][0] : 0.0f;
                sv[m][1] = (1 <= S1) ? V[m][1] : 0.0f;
                sv[m][2] = (1 <= S0) ? V[m][2] : 0.0f;
                sv[m][3] = (1 <= S1) ? V[m][3] : 0.0f;
            } else {
                float t0 = __expf(__ldg(stop + R0));
                float t1 = __expf(__ldg(stop + R1));
                V[m][0] = t0; V[m][1] = t0; V[m][2] = t1; V[m][3] = t1;
                float e00 = __expf(__ldg(em + (size_t)(L0 - 1) * EM_T + (unsigned)b0 * NS + R0));
                float e01 = __expf(__ldg(em + (size_t)(L1 - 1) * EM_T + (unsigned)b1 * NS + R0));
                float e10 = __expf(__ldg(em + (size_t)(L0 - 1) * EM_T + (unsigned)b0 * NS + R1));
                float e11 = __expf(__ldg(em + (size_t)(L1 - 1) * EM_T + (unsigned)b1 * NS + R1));
                sv[m][0] = (1 <= S0) ? V[m][0] * e00 : 0.0f;
                sv[m][1] = (1 <= S1) ? V[m][1] * e01 : 0.0f;
                sv[m][2] = (1 <= S0) ? V[m][2] * e10 : 0.0f;
                sv[m][3] = (1 <= S1) ? V[m][3] * e11 : 0.0f;
            }
        }
        // store tile (even-q lanes pack row pairs via shfl)
#define STORE_TILE(WB_)                                                        \
        do {                                                                   \
            uint32_t* Wb_ = (WB_);                                             \
            _Pragma("unroll")                                                  \
            for (int m = 0; m < 4; m++) {                                      \
                float t0 = __shfl_down_sync(0xffffffffu, sv[m][0], 4);         \
                float t1 = __shfl_down_sync(0xffffffffu, sv[m][1], 4);         \
                float t2 = __shfl_down_sync(0xffffffffu, sv[m][2], 4);         \
                float t3 = __shfl_down_sync(0xffffffffu, sv[m][3], 4);         \
                if (!(q & 1)) {                                                \
                    int kpA = 8 * m + (q >> 1);                                \
                    uint2 u01 = make_uint2(pack_bf2(sv[m][0], t0),             \
                                           pack_bf2(sv[m][1], t1));            \
                    uint2 u23 = make_uint2(pack_bf2(sv[m][2], t2),             \
                                           pack_bf2(sv[m][3], t3));            \
                    *(uint2*)&Wb_[kpA * 8 + 2 * p]       = u01;                \
                    *(uint2*)&Wb_[(kpA + 4) * 8 + 2 * p] = u23;                \
                }                                                              \
            }                                                                  \
        } while (0)

        STORE_TILE(vbuf[dir][0]);
        __syncwarp();

        for (int i = 1; i <= Tmax; i++) {
            const int slot = i & 7;
            const int rp = (i - 1) & 1, wp = i & 1;
            while (ready[dir][slot] < i) { }       // producers run ahead
            __syncwarp();

            const uint32_t* Wr = vbuf[dir][rp];
            unsigned bfr[8];
#pragma unroll
            for (int kt = 0; kt < 4; kt++) {
                bfr[2 * kt]     = Wr[64 * kt + 8 * p + q];
                bfr[2 * kt + 1] = Wr[64 * kt + 32 + 8 * p + q];
            }
            float d[4][4];
#pragma unroll
            for (int m = 0; m < 4; m++) {
                d[m][0] = 0.f; d[m][1] = 0.f; d[m][2] = 0.f; d[m][3] = 0.f;
#pragma unroll
                for (int kt = 0; kt < 4; kt++)
                    mma16816(d[m], afr[m][kt], bfr[2 * kt], bfr[2 * kt + 1]);
            }
            float2 ea[4], eb[4];
#pragma unroll
            for (int m = 0; m < 4; m++) {
                int R0 = 16 * m + q;
                ea[m] = ering[dir][slot][R0][p];
                eb[m] = ering[dir][slot][R0 + 8][p];
            }
            const bool A0 = (i <= S0), A1 = (i <= S1);
#pragma unroll
            for (int m = 0; m < 4; m++) {
                if (dir == 0) {
                    V[m][0] = A0 ? d[m][0] * ea[m].x : V[m][0];
                    V[m][1] = A1 ? d[m][1] * ea[m].y : V[m][1];
                    V[m][2] = A0 ? d[m][2] * eb[m].x : V[m][2];
                    V[m][3] = A1 ? d[m][3] * eb[m].y : V[m][3];
                } else {
                    V[m][0] = A0 ? d[m][0] : V[m][0];
                    V[m][1] = A1 ? d[m][1] : V[m][1];
                    V[m][2] = A0 ? d[m][2] : V[m][2];
                    V[m][3] = A1 ? d[m][3] : V[m][3];
                }
            }
            if ((i & 7) == 0) {                    // rescale every 8 ticks
                float m0 = fmaxf(bf16lo_f(Wr[c0]), 1e-30f);
                float m1 = fmaxf(bf16lo_f(Wr[c1]), 1e-30f);
                float rv0 = A0 ? __fdividef(1.0f, m0) : 1.0f;
                float rv1 = A1 ? __fdividef(1.0f, m1) : 1.0f;
                Ca += A0 ? __logf(m0) : 0.0f;
                Cc += A1 ? __logf(m1) : 0.0f;
#pragma unroll
                for (int m = 0; m < 4; m++) {
                    V[m][0] *= rv0; V[m][2] *= rv0;
                    V[m][1] *= rv1; V[m][3] *= rv1;
                }
            }
            const bool N0 = (i + 1 <= S0), N1 = (i + 1 <= S1);
#pragma unroll
            for (int m = 0; m < 4; m++) {
                if (dir == 0) {
                    sv[m][0] = N0 ? V[m][0] : 0.0f;
                    sv[m][1] = N1 ? V[m][1] : 0.0f;
                    sv[m][2] = N0 ? V[m][2] : 0.0f;
                    sv[m][3] = N1 ? V[m][3] : 0.0f;
                } else {                           // store g = beta * e
                    sv[m][0] = N0 ? V[m][0] * ea[m].x : 0.0f;
                    sv[m][1] = N1 ? V[m][1] * ea[m].y : 0.0f;
                    sv[m][2] = N0 ? V[m][2] * eb[m].x : 0.0f;
                    sv[m][3] = N1 ? V[m][3] * eb[m].y : 0.0f;
                }
            }
            STORE_TILE(vbuf[dir][wp]);
            if (lane == 0) consumed[dir] = i - 1;  // lagged: slot reads done
            __syncwarp();
        }

        // publish meeting state
        float (*meet)[8] = (dir == 0) ? meetA : meetB;
#pragma unroll
        for (int m = 0; m < 4; m++) {
            int R0 = 16 * m + q;
            meet[R0][c0] = V[m][0];     meet[R0][c1] = V[m][1];
            meet[R0 + 8][c0] = V[m][2]; meet[R0 + 8][c1] = V[m][3];
        }
        if (q == 0) { sC[dir][c0] = Ca; sC[dir][c1] = Cc; }
    } else {
        // ============================ PRODUCER ============================
        const int cp = lane & 3, h = lane >> 2;
        const int cA = 2 * cp, cB = cA + 1;
        const int LA = Lsh[cA], LB = Lsh[cB];
        const float* pA = em + (unsigned)bat[cA] * NS + h;
        const float* pB = em + (unsigned)bat[cB] * NS + h;

        float va[3][8], vb[3][8];
#pragma unroll
        for (int s = 0; s < 3; s++) {
            int tp0 = 1 + s;
            int tA = dir ? max(LA - 1 - tp0, 0) : min(tp0, LA - 1);
            int tB = dir ? max(LB - 1 - tp0, 0) : min(tp0, LB - 1);
            const float* qA = pA + (size_t)tA * EM_T;
            const float* qB = pB + (size_t)tB * EM_T;
#pragma unroll
            for (int j = 0; j < 8; j++) {
                va[s][j] = __ldg(qA + 8 * j);
                vb[s][j] = __ldg(qB + 8 * j);
            }
        }
        int tp = 1;
#define PSTEP(s_)                                                              \
        do {                                                                   \
            while (consumed[dir] < tp - 8) { }                                 \
            int slot = tp & 7;                                                 \
            _Pragma("unroll")                                                  \
            for (int j = 0; j < 8; j++)                                        \
                ering[dir][slot][h + 8 * j][cp] =                              \
                    make_float2(__expf(va[s_][j]), __expf(vb[s_][j]));         \
            __syncwarp();                                                      \
            asm volatile("membar.cta;" ::: "memory");                          \
            if (lane == 0) ready[dir][slot] = tp;                              \
            int tn = tp + 3;                                                   \
            if (tn <= Tmax) {                                                  \
                int tA = dir ? max(LA - 1 - tn, 0) : min(tn, LA - 1);          \
                int tB = dir ? max(LB - 1 - tn, 0) : min(tn, LB - 1);          \
                const float* qA = pA + (size_t)tA * EM_T;                      \
                const float* qB = pB + (size_t)tB * EM_T;                      \
                _Pragma("unroll")                                              \
                for (int j = 0; j < 8; j++) {                                  \
                    va[s_][j] = __ldg(qA + 8 * j);                             \
                    vb[s_][j] = __ldg(qB + 8 * j);                             \
                }                                                              \
            }                                                                  \
            tp++;                                                              \
        } while (0)

        while (tp + 2 <= Tmax) { PSTEP(0); PSTEP(1); PSTEP(2); }
        if (tp <= Tmax) PSTEP(0);
        if (tp <= Tmax) PSTEP(1);
        if (tp <= Tmax) PSTEP(2);
    }

    __syncthreads();

    // combine: Z_c = sum_s alpha_m[s][c] * beta_m[s][c]
    if (w == 0) {
        int c = lane >> 2, j = lane & 3;
        float z = 0.0f;
#pragma unroll
        for (int r = 0; r < 16; r++)
            z += meetA[16 * j + r][c] * meetB[16 * j + r][c];
        z += __shfl_xor_sync(0xffffffffu, z, 1);
        z += __shfl_xor_sync(0xffffffffu, z, 2);
        if (j == 0)
            out[bat[c]] = __logf(z) + sC[0][c] + sC[1][c]
                        + SHIFT_C * (float)(Lsh[c] - 1);
    }
}

extern "C" void kernel_launch(void* const* d_in, const int* in_sizes, int n_in,
                              void* d_out, int out_size)
{
    const float* em    = (const float*)d_in[0];
    const int*   seq   = (const int*)d_in[1];
    const float* start = (const float*)d_in[2];
    const float* stop  = (const float*)d_in[3];
    const float* trans = (const float*)d_in[4];
    float*       out   = (float*)d_out;

    rank_kernel<<<BATCH / 128, 128>>>(seq);
    crf_forward_kernel<<<BATCH / 8, 128>>>(em, seq, start, stop, trans, out);
}

// round 16
// speedup vs baseline: 2.5030x; 2.5030x over previous
#include <cuda_runtime.h>
#include <cuda_bf16.h>

#define BATCH    1024
#define NS       64
#define F2_T     (BATCH * NS / 2)   // float2 stride per timestep
#define SHIFT_C  4.5f

__device__ int    g_perm[BATCH];        // rank (desc by length) -> batch index
__device__ float  g_meetF[BATCH][NS];   // fwd alpha at meeting point
__device__ float  g_meetB[BATCH][NS];   // bwd beta at meeting point
__device__ float  g_Cacc[2][BATCH];     // log-scale accumulators

__device__ __forceinline__ __nv_bfloat162 u2b(unsigned u) {
    __nv_bfloat162 r;
    *reinterpret_cast<unsigned*>(&r) = u;
    return r;
}
__device__ __forceinline__ unsigned b2u(__nv_bfloat162 b) {
    return *reinterpret_cast<unsigned*>(&b);
}

// ---- rank by length (descending), ties by index: perm is a bijection ----
__global__ void rank_kernel(const int* __restrict__ seq) {
    __shared__ int len[BATCH];
    const int tid = threadIdx.x;             // 128 threads
    for (int j = tid; j < BATCH; j += 128) len[j] = seq[j];
    __syncthreads();
    const int i  = blockIdx.x * 128 + tid;
    const int li = len[i];
    int r = 0;
#pragma unroll 8
    for (int j = 0; j < BATCH; j++) {
        int lj = len[j];
        r += (int)((lj > li) | ((lj == li) & (j < i)));
    }
    g_perm[r] = i;
}

// 16 warps/block, grid 148. Job j in 0..2047 = (batch g_perm[j>>1], dir j&1),
// sizes descending in j. Serpentine rounds balance per-SMSP step sums.
__global__ void __launch_bounds__(512, 1)
crf_forward_kernel(const float* __restrict__ em,
                   const int*   __restrict__ seq,
                   const float* __restrict__ start,
                   const float* __restrict__ stop,
                   const float* __restrict__ trans,
                   float*       __restrict__ out)
{
    __shared__ unsigned xbuf[16][2][32];     // per-warp exchange, dbl-buffered

    const int w    = threadIdx.x >> 5;       // 0..15
    const int lane = threadIdx.x & 31;
    const int smsp = blockIdx.x * 4 + (w & 3);   // 0..591
    const int rnd  = w >> 2;                     // 0..3

    int j;
    if      (rnd == 0) j = smsp;                  // fwd
    else if (rnd == 1) j = 592  + (591 - smsp);   // rev
    else if (rnd == 2) j = 1184 + (591 - smsp);   // rev
    else               j = 1776 + smsp;           // fwd
    if (j >= 2 * BATCH) return;                   // dummy slot

    const int b   = g_perm[j >> 1];
    const int dir = j & 1;                        // 0 fwd, 1 bwd
    const int L   = seq[b];
    const int nf  = L >> 1;
    const int nb  = L - 1 - nf;
    const int s0  = 2 * lane;

    // ---- one-time E in bf16: fwd uses rows of trans, bwd uses columns ----
    __nv_bfloat162 E0[32], E1[32];
    if (dir == 0) {
        const float4* tr0 = (const float4*)(trans + s0 * NS);
        const float4* tr1 = (const float4*)(trans + (s0 + 1) * NS);
#pragma unroll
        for (int q = 0; q < 16; q++) {
            float4 r0 = __ldg(tr0 + q);
            float4 r1 = __ldg(tr1 + q);
            E0[2 * q]     = __floats2bfloat162_rn(__expf(r0.x - SHIFT_C), __expf(r0.y - SHIFT_C));
            E0[2 * q + 1] = __floats2bfloat162_rn(__expf(r0.z - SHIFT_C), __expf(r0.w - SHIFT_C));
            E1[2 * q]     = __floats2bfloat162_rn(__expf(r1.x - SHIFT_C), __expf(r1.y - SHIFT_C));
            E1[2 * q + 1] = __floats2bfloat162_rn(__expf(r1.z - SHIFT_C), __expf(r1.w - SHIFT_C));
        }
    } else {
#pragma unroll
        for (int k = 0; k < 32; k++) {
            float t00 = __ldg(trans + (2 * k) * NS + s0);
            float t10 = __ldg(trans + (2 * k + 1) * NS + s0);
            float t01 = __ldg(trans + (2 * k) * NS + s0 + 1);
            float t11 = __ldg(trans + (2 * k + 1) * NS + s0 + 1);
            E0[k] = __floats2bfloat162_rn(__expf(t00 - SHIFT_C), __expf(t10 - SHIFT_C));
            E1[k] = __floats2bfloat162_rn(__expf(t01 - SHIFT_C), __expf(t11 - SHIFT_C));
        }
    }

    const float2* embase = (const float2*)em + (unsigned)b * (NS / 2) + lane;
    const __nv_bfloat162 z2 = __floats2bfloat162_rn(0.0f, 0.0f);
    float C = 0.0f;
    float fx, fy;

    // MAC core via per-warp smem broadcast (dbl-buffer P_, one syncwarp).
#define MACX(P_, inpk_, vx_, vy_)                                              \
    do {                                                                       \
        xbuf[w][P_][lane] = (inpk_);                                           \
        __syncwarp();                                                          \
        const uint4* xb = (const uint4*)xbuf[w][P_];                           \
        __nv_bfloat162 a0 = z2, a1 = z2, b0 = z2, b1 = z2;                     \
        _Pragma("unroll")                                                      \
        for (int q = 0; q < 8; q++) {                                          \
            uint4 v = xb[q];                                                   \
            a0 = __hfma2(u2b(v.x), E0[4 * q],     a0);                         \
            b0 = __hfma2(u2b(v.x), E1[4 * q],     b0);                         \
            a1 = __hfma2(u2b(v.y), E0[4 * q + 1], a1);                         \
            b1 = __hfma2(u2b(v.y), E1[4 * q + 1], b1);                         \
            a0 = __hfma2(u2b(v.z), E0[4 * q + 2], a0);                         \
            b0 = __hfma2(u2b(v.z), E1[4 * q + 2], b0);                         \
            a1 = __hfma2(u2b(v.w), E0[4 * q + 3], a1);                         \
            b1 = __hfma2(u2b(v.w), E1[4 * q + 3], b1);                         \
        }                                                                      \
        __nv_bfloat162 A = __hadd2(a0, a1);                                    \
        __nv_bfloat162 B = __hadd2(b0, b1);                                    \
        vx_ = __low2float(A) + __high2float(A);                                \
        vy_ = __low2float(B) + __high2float(B);                                \
    } while (0)

    if (dir == 0) {
        // ================= FORWARD: alpha' = (T·alpha) ∘ e_t =================
        float2 st2 = ((const float2*)start)[lane];
        float2 em0 = __ldg(embase);
        fx = __expf(st2.x + em0.x);
        fy = __expf(st2.y + em0.y);
        unsigned curp = b2u(__floats2bfloat162_rn(fx, fy));

        float2 ring[8];
#pragma unroll
        for (int i = 0; i < 8; i++) {
            int tt = (1 + i < nf) ? (1 + i) : nf;
            ring[i] = __ldg(embase + (unsigned)tt * F2_T);
        }

#define FWD_BODY(eraw_, P_)                                                    \
        do {                                                                   \
            float ex = __expf((eraw_).x);                                      \
            float ey = __expf((eraw_).y);                                      \
            float vx, vy;                                                      \
            MACX(P_, curp, vx, vy);                                            \
            fx = vx * ex;                                                      \
            fy = vy * ey;                                                      \
            curp = b2u(__floats2bfloat162_rn(fx, fy));                         \
        } while (0)

#define FWD_STEP(tcur_, ri_, P_)                                               \
        do {                                                                   \
            float2 eraw = ring[ri_];                                           \
            int tp = (tcur_) + 8;                                              \
            tp = (tp < nf) ? tp : nf;                                          \
            ring[ri_] = __ldg(embase + (unsigned)tp * F2_T);                   \
            FWD_BODY(eraw, P_);                                                \
        } while (0)

        int t = 1;
        for (; t + 7 <= nf; t += 8) {
            FWD_STEP(t,     0, 0);
            FWD_STEP(t + 1, 1, 1);
            FWD_STEP(t + 2, 2, 0);
            FWD_STEP(t + 3, 3, 1);
            FWD_STEP(t + 4, 4, 0);
            FWD_STEP(t + 5, 5, 1);
            FWD_STEP(t + 6, 6, 0);
            FWD_STEP(t + 7, 7, 1);
            float m = __shfl_sync(0xffffffffu, fx, 0);
            m = fmaxf(m, 1e-30f);
            float rv = __fdividef(1.0f, m);
            fx *= rv; fy *= rv;
            curp = b2u(__floats2bfloat162_rn(fx, fy));
            C += __logf(m);
        }
        if (t <= nf) { FWD_BODY(ring[0], 0); t++; }
        if (t <= nf) { FWD_BODY(ring[1], 1); t++; }
        if (t <= nf) { FWD_BODY(ring[2], 0); t++; }
        if (t <= nf) { FWD_BODY(ring[3], 1); t++; }
        if (t <= nf) { FWD_BODY(ring[4], 0); t++; }
        if (t <= nf) { FWD_BODY(ring[5], 1); t++; }
        if (t <= nf) { FWD_BODY(ring[6], 0); }

        ((float2*)g_meetF[b])[lane] = make_float2(fx, fy);
        if (lane == 0) g_Cacc[0][b] = C;
    } else {
        // ================ BACKWARD: beta' = Tᵀ·(beta ∘ e_t) =================
        float2 sp2 = ((const float2*)stop)[lane];
        fx = __expf(sp2.x);
        fy = __expf(sp2.y);

        float2 ring[8];
#pragma unroll
        for (int i = 0; i < 8; i++) {
            int tt = L - 1 - i;
            tt = (tt > 0) ? tt : 0;
            ring[i] = __ldg(embase + (unsigned)tt * F2_T);
        }

#define BWD_BODY(eraw_, P_)                                                    \
        do {                                                                   \
            float gx = fx * __expf((eraw_).x);                                 \
            float gy = fy * __expf((eraw_).y);                                 \
            unsigned gp = b2u(__floats2bfloat162_rn(gx, gy));                  \
            MACX(P_, gp, fx, fy);                                              \
        } while (0)

#define BWD_STEP(tcur_, ri_, P_)                                               \
        do {                                                                   \
            float2 eraw = ring[ri_];                                           \
            int tp = (tcur_) - 8;                                              \
            tp = (tp > 0) ? tp : 0;                                            \
            ring[ri_] = __ldg(embase + (unsigned)tp * F2_T);                   \
            BWD_BODY(eraw, P_);                                                \
        } while (0)

        int i = 0;
        int t = L - 1;
        for (; i + 7 < nb; i += 8, t -= 8) {
            BWD_STEP(t,     0, 0);
            BWD_STEP(t - 1, 1, 1);
            BWD_STEP(t - 2, 2, 0);
            BWD_STEP(t - 3, 3, 1);
            BWD_STEP(t - 4, 4, 0);
            BWD_STEP(t - 5, 5, 1);
            BWD_STEP(t - 6, 6, 0);
            BWD_STEP(t - 7, 7, 1);
            float m = __shfl_sync(0xffffffffu, fx, 0);
            m = fmaxf(m, 1e-30f);
            float rv = __fdividef(1.0f, m);
            fx *= rv; fy *= rv;
            C += __logf(m);
        }
        if (i < nb) { BWD_BODY(ring[0], 0); i++; }
        if (i < nb) { BWD_BODY(ring[1], 1); i++; }
        if (i < nb) { BWD_BODY(ring[2], 0); i++; }
        if (i < nb) { BWD_BODY(ring[3], 1); i++; }
        if (i < nb) { BWD_BODY(ring[4], 0); i++; }
        if (i < nb) { BWD_BODY(ring[5], 1); i++; }
        if (i < nb) { BWD_BODY(ring[6], 0); }

        ((float2*)g_meetB[b])[lane] = make_float2(fx, fy);
        if (lane == 0) g_Cacc[1][b] = C;
    }
}

// combine: logZ_b = log(sum_s alphaM[b][s]*betaM[b][s]) + Cf + Cb + c*(L-1)
__global__ void combine_kernel(const int* __restrict__ seq,
                               float* __restrict__ out)
{
    const int b = blockIdx.x * 128 + threadIdx.x;
    const float4* fa = (const float4*)g_meetF[b];
    const float4* fb = (const float4*)g_meetB[b];
    float z = 0.0f;
#pragma unroll
    for (int q = 0; q < 16; q++) {
        float4 a = fa[q], c = fb[q];
        z += a.x * c.x + a.y * c.y + a.z * c.z + a.w * c.w;
    }
    out[b] = __logf(z) + g_Cacc[0][b] + g_Cacc[1][b]
           + SHIFT_C * (float)(seq[b] - 1);
}

extern "C" void kernel_launch(void* const* d_in, const int* in_sizes, int n_in,
                              void* d_out, int out_size)
{
    const float* em    = (const float*)d_in[0];
    const int*   seq   = (const int*)d_in[1];
    const float* start = (const float*)d_in[2];
    const float* stop  = (const float*)d_in[3];
    const float* trans = (const float*)d_in[4];
    float*       out   = (float*)d_out;

    rank_kernel<<<BATCH / 128, 128>>>(seq);
    crf_forward_kernel<<<148, 512>>>(em, seq, start, stop, trans, out);
    combine_kernel<<<BATCH / 128, 128>>>(seq, out);
}

// round 17
// speedup vs baseline: 2.5507x; 1.0190x over previous
#include <cuda_runtime.h>
#include <cuda_bf16.h>

#define BATCH    1024
#define NS       64
#define F2_T     (BATCH * NS / 2)   // float2 stride per timestep
#define SHIFT_C  4.5f

__device__ int    g_perm[BATCH];        // rank (desc by length) -> batch index
__device__ float  g_meetF[BATCH][NS];   // fwd alpha at meeting point
__device__ float  g_meetB[BATCH][NS];   // bwd beta at meeting point
__device__ float  g_Cacc[2][BATCH];     // log-scale accumulators
__device__ __align__(16) __nv_bfloat16 g_Ef[NS][NS];  // exp(trans-c)
__device__ __align__(16) __nv_bfloat16 g_Eb[NS][NS];  // transpose

__device__ __forceinline__ __nv_bfloat162 u2b(unsigned u) {
    __nv_bfloat162 r;
    *reinterpret_cast<unsigned*>(&r) = u;
    return r;
}
__device__ __forceinline__ unsigned b2u(__nv_bfloat162 b) {
    return *reinterpret_cast<unsigned*>(&b);
}

// ---- prep: histogram rank (desc by length) + bf16 exp(trans-c) matrices ----
__global__ void __launch_bounds__(1024) prep_kernel(const int* __restrict__ seq,
                                                    const float* __restrict__ trans)
{
    __shared__ int cnt[1025];     // counts per length 1..1024
    __shared__ int sa[1024];      // scan array (reversed: sa[t] ~ length 1024-t)
    __shared__ int off[1025];     // per-bucket running offset

    const int tid = threadIdx.x;  // 0..1023

    // E matrices: 4 elements per thread
#pragma unroll
    for (int k = 0; k < 4; k++) {
        int idx = 4 * tid + k;
        int r = idx >> 6, c = idx & 63;
        __nv_bfloat16 v = __float2bfloat16(__expf(trans[idx] - SHIFT_C));
        g_Ef[r][c] = v;
        g_Eb[c][r] = v;
    }

    cnt[tid] = 0;
    off[tid] = 0;
    if (tid == 0) { cnt[1024] = 0; off[1024] = 0; }
    __syncthreads();

    const int li = seq[tid];
    atomicAdd(&cnt[li], 1);
    __syncthreads();

    // reversed inclusive scan: sa[t] = sum_{t'<=t} cnt[1024-t']
    sa[tid] = cnt[1024 - tid];
    __syncthreads();
#pragma unroll
    for (int s = 1; s < 1024; s <<= 1) {
        int v = sa[tid] + ((tid >= s) ? sa[tid - s] : 0);
        __syncthreads();
        sa[tid] = v;
        __syncthreads();
    }
    // base[l] = count of lengths > l = inclusive - own = sa[1024-l] - cnt[l]
    const int base = sa[1024 - li] - cnt[li];
    const int r = base + atomicAdd(&off[li], 1);
    g_perm[r] = tid;
}

// 16 warps/block, grid 148. Job j in 0..2047 = (batch g_perm[j>>1], dir j&1),
// sizes descending in j. Serpentine rounds balance per-SMSP step sums.
__global__ void __launch_bounds__(512, 1)
crf_forward_kernel(const float* __restrict__ em,
                   const int*   __restrict__ seq,
                   const float* __restrict__ start,
                   const float* __restrict__ stop,
                   const float* __restrict__ trans,
                   float*       __restrict__ out)
{
    __shared__ unsigned xbuf[16][2][32];     // per-warp exchange, dbl-buffered

    const int w    = threadIdx.x >> 5;       // 0..15
    const int lane = threadIdx.x & 31;
    const int smsp = blockIdx.x * 4 + (w & 3);   // 0..591
    const int rnd  = w >> 2;                     // 0..3

    int j;
    if      (rnd == 0) j = smsp;                  // fwd
    else if (rnd == 1) j = 592  + (591 - smsp);   // rev
    else if (rnd == 2) j = 1184 + (591 - smsp);   // rev
    else               j = 1776 + smsp;           // fwd
    if (j >= 2 * BATCH) return;                   // dummy slot

    const int b   = g_perm[j >> 1];
    const int dir = j & 1;                        // 0 fwd, 1 bwd
    const int L   = seq[b];
    const int nf  = L >> 1;
    const int nb  = L - 1 - nf;
    const int s0  = 2 * lane;

    // ---- E rows from precomputed bf16 matrices: 16x LDG.128 ----
    __nv_bfloat162 E0[32], E1[32];
    {
        const uint4* p0 = (const uint4*)(dir ? g_Eb[s0]     : g_Ef[s0]);
        const uint4* p1 = (const uint4*)(dir ? g_Eb[s0 + 1] : g_Ef[s0 + 1]);
#pragma unroll
        for (int q = 0; q < 8; q++) {
            uint4 v0 = __ldg(p0 + q);
            uint4 v1 = __ldg(p1 + q);
            E0[4 * q]     = u2b(v0.x); E0[4 * q + 1] = u2b(v0.y);
            E0[4 * q + 2] = u2b(v0.z); E0[4 * q + 3] = u2b(v0.w);
            E1[4 * q]     = u2b(v1.x); E1[4 * q + 1] = u2b(v1.y);
            E1[4 * q + 2] = u2b(v1.z); E1[4 * q + 3] = u2b(v1.w);
        }
    }

    const float2* embase = (const float2*)em + (unsigned)b * (NS / 2) + lane;
    const __nv_bfloat162 z2 = __floats2bfloat162_rn(0.0f, 0.0f);
    float C = 0.0f;
    float fx, fy;

    // MAC core via per-warp smem broadcast (dbl-buffer P_, one syncwarp).
#define MACX(P_, inpk_, vx_, vy_)                                              \
    do {                                                                       \
        xbuf[w][P_][lane] = (inpk_);                                           \
        __syncwarp();                                                          \
        const uint4* xb = (const uint4*)xbuf[w][P_];                           \
        __nv_bfloat162 a0 = z2, a1 = z2, b0 = z2, b1 = z2;                     \
        _Pragma("unroll")                                                      \
        for (int q = 0; q < 8; q++) {                                          \
            uint4 v = xb[q];                                                   \
            a0 = __hfma2(u2b(v.x), E0[4 * q],     a0);                         \
            b0 = __hfma2(u2b(v.x), E1[4 * q],     b0);                         \
            a1 = __hfma2(u2b(v.y), E0[4 * q + 1], a1);                         \
            b1 = __hfma2(u2b(v.y), E1[4 * q + 1], b1);                         \
            a0 = __hfma2(u2b(v.z), E0[4 * q + 2], a0);                         \
            b0 = __hfma2(u2b(v.z), E1[4 * q + 2], b0);                         \
            a1 = __hfma2(u2b(v.w), E0[4 * q + 3], a1);                         \
            b1 = __hfma2(u2b(v.w), E1[4 * q + 3], b1);                         \
        }                                                                      \
        __nv_bfloat162 A = __hadd2(a0, a1);                                    \
        __nv_bfloat162 B = __hadd2(b0, b1);                                    \
        vx_ = __low2float(A) + __high2float(A);                                \
        vy_ = __low2float(B) + __high2float(B);                                \
    } while (0)

    if (dir == 0) {
        // ================= FORWARD: alpha' = (T·alpha) ∘ e_t =================
        float2 st2 = ((const float2*)start)[lane];
        float2 em0 = __ldg(embase);
        fx = __expf(st2.x + em0.x);
        fy = __expf(st2.y + em0.y);
        unsigned curp = b2u(__floats2bfloat162_rn(fx, fy));

        float2 ring[8];
#pragma unroll
        for (int i = 0; i < 8; i++) {
            int tt = (1 + i < nf) ? (1 + i) : nf;
            ring[i] = __ldg(embase + (unsigned)tt * F2_T);
        }

#define FWD_BODY(eraw_, P_)                                                    \
        do {                                                                   \
            float ex = __expf((eraw_).x);                                      \
            float ey = __expf((eraw_).y);                                      \
            float vx, vy;                                                      \
            MACX(P_, curp, vx, vy);                                            \
            fx = vx * ex;                                                      \
            fy = vy * ey;                                                      \
            curp = b2u(__floats2bfloat162_rn(fx, fy));                         \
        } while (0)

#define FWD_STEP(tcur_, ri_, P_)                                               \
        do {                                                                   \
            float2 eraw = ring[ri_];                                           \
            int tp = (tcur_) + 8;                                              \
            tp = (tp < nf) ? tp : nf;                                          \
            ring[ri_] = __ldg(embase + (unsigned)tp * F2_T);                   \
            FWD_BODY(eraw, P_);                                                \
        } while (0)

        int t = 1;
        for (; t + 7 <= nf; t += 8) {
            FWD_STEP(t,     0, 0);
            FWD_STEP(t + 1, 1, 1);
            FWD_STEP(t + 2, 2, 0);
            FWD_STEP(t + 3, 3, 1);
            FWD_STEP(t + 4, 4, 0);
            FWD_STEP(t + 5, 5, 1);
            FWD_STEP(t + 6, 6, 0);
            FWD_STEP(t + 7, 7, 1);
            float m = __shfl_sync(0xffffffffu, fx, 0);
            m = fmaxf(m, 1e-30f);
            float rv = __fdividef(1.0f, m);
            fx *= rv; fy *= rv;
            curp = b2u(__floats2bfloat162_rn(fx, fy));
            C += __logf(m);
        }
        if (t <= nf) { FWD_BODY(ring[0], 0); t++; }
        if (t <= nf) { FWD_BODY(ring[1], 1); t++; }
        if (t <= nf) { FWD_BODY(ring[2], 0); t++; }
        if (t <= nf) { FWD_BODY(ring[3], 1); t++; }
        if (t <= nf) { FWD_BODY(ring[4], 0); t++; }
        if (t <= nf) { FWD_BODY(ring[5], 1); t++; }
        if (t <= nf) { FWD_BODY(ring[6], 0); }

        ((float2*)g_meetF[b])[lane] = make_float2(fx, fy);
        if (lane == 0) g_Cacc[0][b] = C;
    } else {
        // ================ BACKWARD: beta' = Tᵀ·(beta ∘ e_t) =================
        float2 sp2 = ((const float2*)stop)[lane];
        fx = __expf(sp2.x);
        fy = __expf(sp2.y);

        float2 ring[8];
#pragma unroll
        for (int i = 0; i < 8; i++) {
            int tt = L - 1 - i;
            tt = (tt > 0) ? tt : 0;
            ring[i] = __ldg(embase + (unsigned)tt * F2_T);
        }

#define BWD_BODY(eraw_, P_)                                                    \
        do {                                                                   \
            float gx = fx * __expf((eraw_).x);                                 \
            float gy = fy * __expf((eraw_).y);                                 \
            unsigned gp = b2u(__floats2bfloat162_rn(gx, gy));                  \
            MACX(P_, gp, fx, fy);                                              \
        } while (0)

#define BWD_STEP(tcur_, ri_, P_)                                               \
        do {                                                                   \
            float2 eraw = ring[ri_];                                           \
            int tp = (tcur_) - 8;                                              \
            tp = (tp > 0) ? tp : 0;                                            \
            ring[ri_] = __ldg(embase + (unsigned)tp * F2_T);                   \
            BWD_BODY(eraw, P_);                                                \
        } while (0)

        int i = 0;
        int t = L - 1;
        for (; i + 7 < nb; i += 8, t -= 8) {
            BWD_STEP(t,     0, 0);
            BWD_STEP(t - 1, 1, 1);
            BWD_STEP(t - 2, 2, 0);
            BWD_STEP(t - 3, 3, 1);
            BWD_STEP(t - 4, 4, 0);
            BWD_STEP(t - 5, 5, 1);
            BWD_STEP(t - 6, 6, 0);
            BWD_STEP(t - 7, 7, 1);
            float m = __shfl_sync(0xffffffffu, fx, 0);
            m = fmaxf(m, 1e-30f);
            float rv = __fdividef(1.0f, m);
            fx *= rv; fy *= rv;
            C += __logf(m);
        }
        if (i < nb) { BWD_BODY(ring[0], 0); i++; }
        if (i < nb) { BWD_BODY(ring[1], 1); i++; }
        if (i < nb) { BWD_BODY(ring[2], 0); i++; }
        if (i < nb) { BWD_BODY(ring[3], 1); i++; }
        if (i < nb) { BWD_BODY(ring[4], 0); i++; }
        if (i < nb) { BWD_BODY(ring[5], 1); i++; }
        if (i < nb) { BWD_BODY(ring[6], 0); }

        ((float2*)g_meetB[b])[lane] = make_float2(fx, fy);
        if (lane == 0) g_Cacc[1][b] = C;
    }
}

// combine: logZ_b = log(sum_s alphaM[b][s]*betaM[b][s]) + Cf + Cb + c*(L-1)
__global__ void combine_kernel(const int* __restrict__ seq,
                               float* __restrict__ out)
{
    const int b = blockIdx.x * 128 + threadIdx.x;
    const float4* fa = (const float4*)g_meetF[b];
    const float4* fb = (const float4*)g_meetB[b];
    float z = 0.0f;
#pragma unroll
    for (int q = 0; q < 16; q++) {
        float4 a = fa[q], c = fb[q];
        z += a.x * c.x + a.y * c.y + a.z * c.z + a.w * c.w;
    }
    out[b] = __logf(z) + g_Cacc[0][b] + g_Cacc[1][b]
           + SHIFT_C * (float)(seq[b] - 1);
}

extern "C" void kernel_launch(void* const* d_in, const int* in_sizes, int n_in,
                              void* d_out, int out_size)
{
    const float* em    = (const float*)d_in[0];
    const int*   seq   = (const int*)d_in[1];
    const float* start = (const float*)d_in[2];
    const float* stop  = (const float*)d_in[3];
    const float* trans = (const float*)d_in[4];
    float*       out   = (float*)d_out;

    prep_kernel<<<1, 1024>>>(seq, trans);
    crf_forward_kernel<<<148, 512>>>(em, seq, start, stop, trans, out);
    combine_kernel<<<BATCH / 128, 128>>>(seq, out);
}